// round 15
// baseline (speedup 1.0000x reference)
#include <cuda_runtime.h>

#define NN 100000
#define HH 32
#define FF 64
#define GG 256
#define CC 10
#define BN_EPS 1e-5f
#define SB ((NN + 1023) / 1024)
#define NPW 4

// ---------------- scratch (static device globals) ----------------
__device__ int   g_row[NN + 1];
__device__ int   g_cur[NN];
__device__ int   g_col[1600000 + NN];    // +NN for self-loops
__device__ int   g_part[SB];
__device__ float g_p[(size_t)NN * HH];
__device__ float g_z[(size_t)NN * HH];
__device__ float g_stats[5 * 2 * HH];    // per-layer sum/sumsq slots
__device__ float g_pool[GG * HH];

// ---------------- CSR build ----------------
// hist: 4 edges per thread via one int4 load.
__global__ void hist_k(const int* __restrict__ dst, int* __restrict__ deg, int E) {
    int t = blockIdx.x * blockDim.x + threadIdx.x;
    int i = t * 4;
    if (i + 4 <= E) {
        int4 d = *reinterpret_cast<const int4*>(dst + i);
        atomicAdd(&deg[d.x], 1);
        atomicAdd(&deg[d.y], 1);
        atomicAdd(&deg[d.z], 1);
        atomicAdd(&deg[d.w], 1);
    } else {
        for (; i < E; i++) atomicAdd(&deg[dst[i]], 1);
    }
}

// scans operate on deg+1 (self-loop included in every node's count)
__global__ void scanA_k(const int* __restrict__ deg, int* __restrict__ part) {
    int i = blockIdx.x * 1024 + threadIdx.x;
    int v = (i < NN) ? (deg[i] + 1) : 0;
    #pragma unroll
    for (int o = 16; o; o >>= 1) v += __shfl_down_sync(0xffffffffu, v, o);
    __shared__ int ws[32];
    if ((threadIdx.x & 31) == 0) ws[threadIdx.x >> 5] = v;
    __syncthreads();
    if (threadIdx.x < 32) {
        int s = ws[threadIdx.x];
        #pragma unroll
        for (int o = 16; o; o >>= 1) s += __shfl_down_sync(0xffffffffu, s, o);
        if (threadIdx.x == 0) part[blockIdx.x] = s;
    }
}

__global__ void scanB_k(int* __restrict__ part, int nb) {
    if (threadIdx.x == 0) {
        int a = 0;
        for (int i = 0; i < nb; i++) { int t = part[i]; part[i] = a; a += t; }
    }
}

// scanC: exclusive scan of (deg+1); seeds col[row[i]] = i (self-loop) and
// sets cursor past it.
__global__ void scanC_k(int* __restrict__ deg, const int* __restrict__ part,
                        int* __restrict__ row, int* __restrict__ col, int E) {
    int tid = threadIdx.x;
    int i = blockIdx.x * 1024 + tid;
    int v = (i < NN) ? (deg[i] + 1) : 0;
    int lane = tid & 31, wid = tid >> 5;
    int x = v;
    #pragma unroll
    for (int o = 1; o < 32; o <<= 1) {
        int y = __shfl_up_sync(0xffffffffu, x, o);
        if (lane >= o) x += y;
    }
    __shared__ int wsum[32];
    if (lane == 31) wsum[wid] = x;
    __syncthreads();
    if (wid == 0) {
        int w = wsum[lane];
        #pragma unroll
        for (int o = 1; o < 32; o <<= 1) {
            int y = __shfl_up_sync(0xffffffffu, w, o);
            if (lane >= o) w += y;
        }
        wsum[lane] = w;
    }
    __syncthreads();
    int excl = x - v + (wid > 0 ? wsum[wid - 1] : 0) + part[blockIdx.x];
    if (i < NN) {
        row[i] = excl;
        col[excl] = i;          // self-loop occupies slot 0 of the row
        deg[i] = excl + 1;      // cursor starts after self
    }
    if (i == 0) row[NN] = E + NN;
}

// fill: 4 edges per thread via int4 loads of src and dst.
__global__ void fill_k(const int* __restrict__ src, const int* __restrict__ dst,
                       int* __restrict__ cur, int* __restrict__ col, int E) {
    int t = blockIdx.x * blockDim.x + threadIdx.x;
    int i = t * 4;
    if (i + 4 <= E) {
        int4 d = *reinterpret_cast<const int4*>(dst + i);
        int4 s = *reinterpret_cast<const int4*>(src + i);
        col[atomicAdd(&cur[d.x], 1)] = s.x;
        col[atomicAdd(&cur[d.y], 1)] = s.y;
        col[atomicAdd(&cur[d.z], 1)] = s.z;
        col[atomicAdd(&cur[d.w], 1)] = s.w;
    } else {
        for (; i < E; i++) {
            int pos = atomicAdd(&cur[dst[i]], 1);
            col[pos] = src[i];
        }
    }
}

// ---------------- block-1 pre-transform: p = x @ w1a ----------------
__global__ void __launch_bounds__(256) xform_k(const float* __restrict__ x,
                                               const float* __restrict__ w,
                                               float* __restrict__ p) {
    __shared__ __align__(16) float sw[FF * HH];
    for (int i = threadIdx.x; i < FF * HH; i += 256) sw[i] = w[i];
    __syncthreads();
    int n = blockIdx.x * 256 + threadIdx.x;
    if (n >= NN) return;
    float acc[HH];
    #pragma unroll
    for (int j = 0; j < HH; j++) acc[j] = 0.0f;
    const float4* xr = reinterpret_cast<const float4*>(x) + (size_t)n * (FF / 4);
    #pragma unroll
    for (int k4 = 0; k4 < FF / 4; k4++) {
        float4 xv = xr[k4];
        float in4[4] = {xv.x, xv.y, xv.z, xv.w};
        #pragma unroll
        for (int kk = 0; kk < 4; kk++) {
            float v = in4[kk];
            const float4* wr = reinterpret_cast<const float4*>(&sw[(k4 * 4 + kk) * HH]);
            #pragma unroll
            for (int j = 0; j < HH / 4; j++) {
                float4 w4 = wr[j];
                acc[4*j+0] += v * w4.x; acc[4*j+1] += v * w4.y;
                acc[4*j+2] += v * w4.z; acc[4*j+3] += v * w4.w;
            }
        }
    }
    float4* pr = reinterpret_cast<float4*>(p) + (size_t)n * (HH / 4);
    #pragma unroll
    for (int j = 0; j < HH / 4; j++)
        pr[j] = make_float4(acc[4*j], acc[4*j+1], acc[4*j+2], acc[4*j+3]);
}

// ---------------- fused gather + MLP tail + BN stats ----------------
// R11 winner loop; self-contribution now comes via the CSR self-loop, so the
// tail has NO dependent global load between gather and MLP.
__global__ void __launch_bounds__(256) gmlp_k(
    const float* __restrict__ p, const int* __restrict__ row, const int* __restrict__ col,
    const float* __restrict__ wb, const float* __restrict__ ba, const float* __restrict__ bb,
    float* __restrict__ z, float* __restrict__ stats)
{
    __shared__ __align__(16) float sv[8][4][HH];
    __shared__ float sstat[2 * HH];
    const int tid = threadIdx.x, warp = tid >> 5, lane = tid & 31;
    const int grp = lane >> 3, q = lane & 7;
    if (tid < 2 * HH) sstat[tid] = 0.0f;
    float wbc[HH];
    #pragma unroll
    for (int k = 0; k < HH; k++) wbc[k] = wb[k * HH + lane];
    const float bav = ba[lane], bbv = bb[lane];
    const float4* p4 = reinterpret_cast<const float4*>(p);
    __syncthreads();

    const int base = (blockIdx.x * 8 + warp) * 4;   // grid sized so base+3 < NN
    const int n = base + grp;
    const int beg = __ldg(&row[n]), end = __ldg(&row[n + 1]);

    float4 acc0 = make_float4(0.f, 0.f, 0.f, 0.f);
    float4 acc1 = make_float4(0.f, 0.f, 0.f, 0.f);
    int i = beg;
    for (; i + 4 <= end; i += 4) {
        int s0 = __ldg(&col[i + 0]);
        int s1 = __ldg(&col[i + 1]);
        int s2 = __ldg(&col[i + 2]);
        int s3 = __ldg(&col[i + 3]);
        float4 v0 = __ldg(&p4[(size_t)s0 * 8 + q]);
        float4 v1 = __ldg(&p4[(size_t)s1 * 8 + q]);
        float4 v2 = __ldg(&p4[(size_t)s2 * 8 + q]);
        float4 v3 = __ldg(&p4[(size_t)s3 * 8 + q]);
        acc0.x += v0.x + v1.x; acc0.y += v0.y + v1.y;
        acc0.z += v0.z + v1.z; acc0.w += v0.w + v1.w;
        acc1.x += v2.x + v3.x; acc1.y += v2.y + v3.y;
        acc1.z += v2.z + v3.z; acc1.w += v2.w + v3.w;
    }
    for (; i < end; i++) {
        int s = __ldg(&col[i]);
        float4 v = __ldg(&p4[(size_t)s * 8 + q]);
        acc0.x += v.x; acc0.y += v.y; acc0.z += v.z; acc0.w += v.w;
    }
    acc0.x += acc1.x; acc0.y += acc1.y; acc0.z += acc1.z; acc0.w += acc1.w;
    // each lane holds the complete sum (incl. self) for features [4q,4q+4)
    reinterpret_cast<float4*>(&sv[warp][grp][0])[q] = acc0;
    __syncwarp();

    // bias + relu for the 4 nodes (lane = feature) — no global load here
    #pragma unroll
    for (int m = 0; m < 4; m++) {
        float v = fmaxf(sv[warp][m][lane] + bav, 0.0f);
        __syncwarp();
        sv[warp][m][lane] = v;
    }
    __syncwarp();

    float ssum = 0.0f, ssq = 0.0f;
    #pragma unroll
    for (int m = 0; m < 4; m++) {
        float o = bbv;
        const float4* vv = reinterpret_cast<const float4*>(&sv[warp][m][0]);
        #pragma unroll
        for (int k = 0; k < HH / 4; k++) {
            float4 v4 = vv[k];
            o += v4.x * wbc[4*k+0] + v4.y * wbc[4*k+1]
               + v4.z * wbc[4*k+2] + v4.w * wbc[4*k+3];
        }
        o = fmaxf(o, 0.0f);
        z[(size_t)(base + m) * HH + lane] = o;
        ssum += o; ssq += o * o;
    }
    atomicAdd(&sstat[lane], ssum);
    atomicAdd(&sstat[HH + lane], ssq);
    __syncthreads();
    if (tid < 2 * HH) atomicAdd(&stats[tid], sstat[tid]);
}

// ---------------- BN apply + next-layer pre-transform: p = BN(z) @ wa ----------------
__global__ void __launch_bounds__(256) bnx_k(
    const float* __restrict__ z, const float* __restrict__ stats,
    const float* __restrict__ gamma, const float* __restrict__ beta,
    const float* __restrict__ wa, float* __restrict__ p)
{
    __shared__ __align__(16) float sv[8][HH];
    const int tid = threadIdx.x, warp = tid >> 5, lane = tid & 31;
    float wac[HH];
    #pragma unroll
    for (int k = 0; k < HH; k++) wac[k] = wa[k * HH + lane];
    float mean  = stats[lane] * (1.0f / NN);
    float var   = stats[HH + lane] * (1.0f / NN) - mean * mean;
    float scale = gamma[lane] * rsqrtf(var + BN_EPS);
    float shift = beta[lane] - mean * scale;
    const int base = (blockIdx.x * 8 + warp) * NPW;
    for (int it = 0; it < NPW; it++) {
        int n = base + it;
        if (n >= NN) break;
        float h = z[(size_t)n * HH + lane] * scale + shift;
        sv[warp][lane] = h;
        __syncwarp();
        float o = 0.0f;
        const float4* vv = reinterpret_cast<const float4*>(&sv[warp][0]);
        #pragma unroll
        for (int q = 0; q < HH / 4; q++) {
            float4 v4 = vv[q];
            o += v4.x * wac[4*q+0] + v4.y * wac[4*q+1]
               + v4.z * wac[4*q+2] + v4.w * wac[4*q+3];
        }
        p[(size_t)n * HH + lane] = o;
        __syncwarp();
    }
}

// ---------------- final BN apply + global mean-pool sums ----------------
__global__ void __launch_bounds__(256) bnp_k(
    const float* __restrict__ z, const float* __restrict__ stats,
    const float* __restrict__ gamma, const float* __restrict__ beta,
    const int* __restrict__ batch, float* __restrict__ pool)
{
    __shared__ __align__(16) float sv[8][HH];
    const int tid = threadIdx.x, warp = tid >> 5, lane = tid & 31;
    float mean  = stats[lane] * (1.0f / NN);
    float var   = stats[HH + lane] * (1.0f / NN) - mean * mean;
    float scale = gamma[lane] * rsqrtf(var + BN_EPS);
    float shift = beta[lane] - mean * scale;
    const int base = (blockIdx.x * 8 + warp) * NPW;
    for (int it = 0; it < NPW; it++) {
        int n = base + it;
        if (n >= NN) break;
        float h = z[(size_t)n * HH + lane] * scale + shift;
        sv[warp][lane] = h;
        __syncwarp();
        int g = __ldg(&batch[n]);
        if (lane < HH / 4) {
            float4 v4 = reinterpret_cast<const float4*>(&sv[warp][0])[lane];
            float* a = pool + (size_t)g * HH + lane * 4;
            asm volatile("red.global.add.v4.f32 [%0], {%1,%2,%3,%4};"
                         :: "l"(a), "f"(v4.x), "f"(v4.y), "f"(v4.z), "f"(v4.w) : "memory");
        }
        __syncwarp();
    }
}

// ---------------- head ----------------
__global__ void head_k(const float* __restrict__ pool, const int* __restrict__ batch,
                       const float* __restrict__ fc1w, const float* __restrict__ fc1b,
                       const float* __restrict__ fc2w, const float* __restrict__ fc2b,
                       float* __restrict__ out)
{
    __shared__ float s1[HH * HH], s2[HH * CC], b1[HH], b2[CC];
    const int tid = threadIdx.x;
    for (int i = tid; i < HH * HH; i += GG) s1[i] = fc1w[i];
    for (int i = tid; i < HH * CC; i += GG) s2[i] = fc2w[i];
    if (tid < HH) b1[tid] = fc1b[tid];
    if (tid < CC) b2[tid] = fc2b[tid];
    __syncthreads();
    const int g = tid;
    int lo0 = 0, hi0 = NN;
    while (lo0 < hi0) { int mid = (lo0 + hi0) >> 1; if (batch[mid] < g) lo0 = mid + 1; else hi0 = mid; }
    int lo1 = lo0, hi1 = NN;
    while (lo1 < hi1) { int mid = (lo1 + hi1) >> 1; if (batch[mid] < g + 1) lo1 = mid + 1; else hi1 = mid; }
    float inv = 1.0f / fmaxf((float)(lo1 - lo0), 1.0f);
    float hid[HH];
    #pragma unroll
    for (int j = 0; j < HH; j++) hid[j] = b1[j];
    #pragma unroll
    for (int k = 0; k < HH; k++) {
        float v = pool[g * HH + k] * inv;
        #pragma unroll
        for (int j = 0; j < HH; j++) hid[j] += v * s1[k * HH + j];
    }
    #pragma unroll
    for (int j = 0; j < HH; j++) hid[j] = fmaxf(hid[j], 0.0f);
    float o[CC];
    #pragma unroll
    for (int c = 0; c < CC; c++) o[c] = b2[c];
    #pragma unroll
    for (int k = 0; k < HH; k++) {
        float v = hid[k];
        #pragma unroll
        for (int c = 0; c < CC; c++) o[c] += v * s2[k * CC + c];
    }
    float m = o[0];
    #pragma unroll
    for (int c = 1; c < CC; c++) m = fmaxf(m, o[c]);
    float sum = 0.0f;
    #pragma unroll
    for (int c = 0; c < CC; c++) sum += expf(o[c] - m);
    float lse = m + logf(sum);
    #pragma unroll
    for (int c = 0; c < CC; c++) out[g * CC + c] = o[c] - lse;
}

// ---------------- launch ----------------
extern "C" void kernel_launch(void* const* d_in, const int* in_sizes, int n_in,
                              void* d_out, int out_size)
{
    const float* x     = (const float*)d_in[0];
    const int*   ei    = (const int*)  d_in[1];
    const int*   batch = (const int*)  d_in[2];
    const float* w1a   = (const float*)d_in[3];
    const float* b1a   = (const float*)d_in[4];
    const float* w1b   = (const float*)d_in[5];
    const float* b1b   = (const float*)d_in[6];
    const float* wa    = (const float*)d_in[7];
    const float* ba    = (const float*)d_in[8];
    const float* wb    = (const float*)d_in[9];
    const float* bb    = (const float*)d_in[10];
    const float* gamma = (const float*)d_in[11];
    const float* beta  = (const float*)d_in[12];
    const float* fc1w  = (const float*)d_in[13];
    const float* fc1b  = (const float*)d_in[14];
    const float* fc2w  = (const float*)d_in[15];
    const float* fc2b  = (const float*)d_in[16];
    float* out = (float*)d_out;

    const int E = in_sizes[1] / 2;
    const int* src = ei;
    const int* dst = ei + E;

    int *row, *cur, *col, *part;
    float *p, *z, *stats, *pool;
    cudaGetSymbolAddress((void**)&row,   g_row);
    cudaGetSymbolAddress((void**)&cur,   g_cur);
    cudaGetSymbolAddress((void**)&col,   g_col);
    cudaGetSymbolAddress((void**)&part,  g_part);
    cudaGetSymbolAddress((void**)&p,     g_p);
    cudaGetSymbolAddress((void**)&z,     g_z);
    cudaGetSymbolAddress((void**)&stats, g_stats);
    cudaGetSymbolAddress((void**)&pool,  g_pool);

    // ---- one-time zeroing (off the per-layer critical path) ----
    cudaMemsetAsync(cur,   0, NN * sizeof(int));
    cudaMemsetAsync(stats, 0, 5 * 2 * HH * sizeof(float));
    cudaMemsetAsync(pool,  0, GG * HH * sizeof(float));

    // ---- CSR build (hist/fill vectorized; self-loops seeded in scanC) ----
    const int ET = (E + 3) / 4;
    hist_k <<<(ET + 255) / 256, 256>>>(dst, cur, E);
    scanA_k<<<SB, 1024>>>(cur, part);
    scanB_k<<<1, 32>>>(part, SB);
    scanC_k<<<SB, 1024>>>(cur, part, row, col, E);
    fill_k <<<(ET + 255) / 256, 256>>>(src, dst, cur, col, E);

    // ---- block-1 pre-transform ----
    xform_k<<<(NN + 255) / 256, 256>>>(x, w1a, p);

    const int GB = NN / 32;   // 3125 blocks; 8 warps x 4 nodes

    // ---- 5 GIN blocks (per-layer stats slots; no inter-layer memsets) ----
    for (int i = 0; i < 5; i++) {
        const float* ba_i = (i == 0) ? b1a : ba + (size_t)(i - 1) * HH;
        const float* wb_i = (i == 0) ? w1b : wb + (size_t)(i - 1) * HH * HH;
        const float* bb_i = (i == 0) ? b1b : bb + (size_t)(i - 1) * HH;
        gmlp_k<<<GB, 256>>>(p, row, col, wb_i, ba_i, bb_i, z,
                            stats + (size_t)i * 2 * HH);
        if (i < 4) {
            bnx_k<<<GB, 256>>>(z, stats + (size_t)i * 2 * HH,
                               gamma + (size_t)i * HH, beta + (size_t)i * HH,
                               wa + (size_t)i * HH * HH, p);
        } else {
            bnp_k<<<GB, 256>>>(z, stats + 4 * 2 * HH,
                               gamma + 4 * HH, beta + 4 * HH, batch, pool);
        }
    }

    // ---- readout ----
    head_k<<<1, GG>>>(pool, batch, fc1w, fc1b, fc2w, fc2b, out);
}

// round 16
// speedup vs baseline: 1.0868x; 1.0868x over previous
#include <cuda_runtime.h>

#define NN 100000
#define HH 32
#define FF 64
#define GG 256
#define CC 10
#define BN_EPS 1e-5f
#define SB ((NN + 1023) / 1024)
#define NPW 4

// ---------------- scratch (static device globals) ----------------
__device__ int   g_row[NN + 1];
__device__ int   g_cur[NN];
__device__ int   g_col[1600000];
__device__ int   g_part[SB];
__device__ float g_p[(size_t)NN * HH];
__device__ float g_z[(size_t)NN * HH];
__device__ float g_stats[5 * 2 * HH];    // per-layer sum/sumsq slots
__device__ float g_pool[GG * HH];

// ---------------- CSR build ----------------
__global__ void hist_k(const int* __restrict__ dst, int* __restrict__ deg, int E) {
    int i = blockIdx.x * blockDim.x + threadIdx.x;
    if (i < E) atomicAdd(&deg[dst[i]], 1);
}

__global__ void scanA_k(const int* __restrict__ deg, int* __restrict__ part) {
    int i = blockIdx.x * 1024 + threadIdx.x;
    int v = (i < NN) ? deg[i] : 0;
    #pragma unroll
    for (int o = 16; o; o >>= 1) v += __shfl_down_sync(0xffffffffu, v, o);
    __shared__ int ws[32];
    if ((threadIdx.x & 31) == 0) ws[threadIdx.x >> 5] = v;
    __syncthreads();
    if (threadIdx.x < 32) {
        int s = ws[threadIdx.x];
        #pragma unroll
        for (int o = 16; o; o >>= 1) s += __shfl_down_sync(0xffffffffu, s, o);
        if (threadIdx.x == 0) part[blockIdx.x] = s;
    }
}

__global__ void scanB_k(int* __restrict__ part, int nb) {
    if (threadIdx.x == 0) {
        int a = 0;
        for (int i = 0; i < nb; i++) { int t = part[i]; part[i] = a; a += t; }
    }
}

__global__ void scanC_k(int* __restrict__ deg, const int* __restrict__ part,
                        int* __restrict__ row, int E) {
    int tid = threadIdx.x;
    int i = blockIdx.x * 1024 + tid;
    int v = (i < NN) ? deg[i] : 0;
    int lane = tid & 31, wid = tid >> 5;
    int x = v;
    #pragma unroll
    for (int o = 1; o < 32; o <<= 1) {
        int y = __shfl_up_sync(0xffffffffu, x, o);
        if (lane >= o) x += y;
    }
    __shared__ int wsum[32];
    if (lane == 31) wsum[wid] = x;
    __syncthreads();
    if (wid == 0) {
        int w = wsum[lane];
        #pragma unroll
        for (int o = 1; o < 32; o <<= 1) {
            int y = __shfl_up_sync(0xffffffffu, w, o);
            if (lane >= o) w += y;
        }
        wsum[lane] = w;
    }
    __syncthreads();
    int excl = x - v + (wid > 0 ? wsum[wid - 1] : 0) + part[blockIdx.x];
    if (i < NN) { row[i] = excl; deg[i] = excl; }
    if (i == 0) row[NN] = E;
}

__global__ void fill_k(const int* __restrict__ src, const int* __restrict__ dst,
                       int* __restrict__ cur, int* __restrict__ col, int E) {
    int i = blockIdx.x * blockDim.x + threadIdx.x;
    if (i < E) {
        int d = dst[i];
        int pos = atomicAdd(&cur[d], 1);
        col[pos] = src[i];
    }
}

// ---------------- block-1 pre-transform: p = x @ w1a ----------------
__global__ void __launch_bounds__(256) xform_k(const float* __restrict__ x,
                                               const float* __restrict__ w,
                                               float* __restrict__ p) {
    __shared__ __align__(16) float sw[FF * HH];
    for (int i = threadIdx.x; i < FF * HH; i += 256) sw[i] = w[i];
    __syncthreads();
    int n = blockIdx.x * 256 + threadIdx.x;
    if (n >= NN) return;
    float acc[HH];
    #pragma unroll
    for (int j = 0; j < HH; j++) acc[j] = 0.0f;
    const float4* xr = reinterpret_cast<const float4*>(x) + (size_t)n * (FF / 4);
    #pragma unroll
    for (int k4 = 0; k4 < FF / 4; k4++) {
        float4 xv = xr[k4];
        float in4[4] = {xv.x, xv.y, xv.z, xv.w};
        #pragma unroll
        for (int kk = 0; kk < 4; kk++) {
            float v = in4[kk];
            const float4* wr = reinterpret_cast<const float4*>(&sw[(k4 * 4 + kk) * HH]);
            #pragma unroll
            for (int j = 0; j < HH / 4; j++) {
                float4 w4 = wr[j];
                acc[4*j+0] += v * w4.x; acc[4*j+1] += v * w4.y;
                acc[4*j+2] += v * w4.z; acc[4*j+3] += v * w4.w;
            }
        }
    }
    float4* pr = reinterpret_cast<float4*>(p) + (size_t)n * (HH / 4);
    #pragma unroll
    for (int j = 0; j < HH / 4; j++)
        pr[j] = make_float4(acc[4*j], acc[4*j+1], acc[4*j+2], acc[4*j+3]);
}

// ---------------- fused gather + MLP tail + BN stats (R11 winner, byte-identical) ----------------
// 4 nodes per warp, concurrently: each 8-lane group owns one node's chain
// (8 lanes x float4 = full 32-float row). 4 independent dependency chains per
// warp; per-warp weights/stat/tail costs amortize over 4 nodes.
__global__ void __launch_bounds__(256) gmlp_k(
    const float* __restrict__ p, const int* __restrict__ row, const int* __restrict__ col,
    const float* __restrict__ wb, const float* __restrict__ ba, const float* __restrict__ bb,
    float* __restrict__ z, float* __restrict__ stats)
{
    __shared__ __align__(16) float sv[8][4][HH];
    __shared__ float sstat[2 * HH];
    const int tid = threadIdx.x, warp = tid >> 5, lane = tid & 31;
    const int grp = lane >> 3, q = lane & 7;
    if (tid < 2 * HH) sstat[tid] = 0.0f;
    float wbc[HH];
    #pragma unroll
    for (int k = 0; k < HH; k++) wbc[k] = wb[k * HH + lane];
    const float bav = ba[lane], bbv = bb[lane];
    const float4* p4 = reinterpret_cast<const float4*>(p);
    __syncthreads();

    const int base = (blockIdx.x * 8 + warp) * 4;   // grid sized so base+3 < NN
    const int n = base + grp;
    const int beg = __ldg(&row[n]), end = __ldg(&row[n + 1]);

    float4 acc0 = make_float4(0.f, 0.f, 0.f, 0.f);
    float4 acc1 = make_float4(0.f, 0.f, 0.f, 0.f);
    int i = beg;
    for (; i + 4 <= end; i += 4) {
        int s0 = __ldg(&col[i + 0]);
        int s1 = __ldg(&col[i + 1]);
        int s2 = __ldg(&col[i + 2]);
        int s3 = __ldg(&col[i + 3]);
        float4 v0 = __ldg(&p4[(size_t)s0 * 8 + q]);
        float4 v1 = __ldg(&p4[(size_t)s1 * 8 + q]);
        float4 v2 = __ldg(&p4[(size_t)s2 * 8 + q]);
        float4 v3 = __ldg(&p4[(size_t)s3 * 8 + q]);
        acc0.x += v0.x + v1.x; acc0.y += v0.y + v1.y;
        acc0.z += v0.z + v1.z; acc0.w += v0.w + v1.w;
        acc1.x += v2.x + v3.x; acc1.y += v2.y + v3.y;
        acc1.z += v2.z + v3.z; acc1.w += v2.w + v3.w;
    }
    for (; i < end; i++) {
        int s = __ldg(&col[i]);
        float4 v = __ldg(&p4[(size_t)s * 8 + q]);
        acc0.x += v.x; acc0.y += v.y; acc0.z += v.z; acc0.w += v.w;
    }
    acc0.x += acc1.x; acc0.y += acc1.y; acc0.z += acc1.z; acc0.w += acc1.w;
    // each lane holds the complete sum for features [4q,4q+4) of node base+grp
    reinterpret_cast<float4*>(&sv[warp][grp][0])[q] = acc0;
    __syncwarp();

    // self + bias + relu for the 4 nodes (lane = feature)
    #pragma unroll
    for (int m = 0; m < 4; m++) {
        float v = fmaxf(sv[warp][m][lane] + __ldg(&p[(size_t)(base + m) * HH + lane]) + bav, 0.0f);
        __syncwarp();
        sv[warp][m][lane] = v;
    }
    __syncwarp();

    float ssum = 0.0f, ssq = 0.0f;
    #pragma unroll
    for (int m = 0; m < 4; m++) {
        float o = bbv;
        const float4* vv = reinterpret_cast<const float4*>(&sv[warp][m][0]);
        #pragma unroll
        for (int k = 0; k < HH / 4; k++) {
            float4 v4 = vv[k];
            o += v4.x * wbc[4*k+0] + v4.y * wbc[4*k+1]
               + v4.z * wbc[4*k+2] + v4.w * wbc[4*k+3];
        }
        o = fmaxf(o, 0.0f);
        z[(size_t)(base + m) * HH + lane] = o;
        ssum += o; ssq += o * o;
    }
    atomicAdd(&sstat[lane], ssum);
    atomicAdd(&sstat[HH + lane], ssq);
    __syncthreads();
    if (tid < 2 * HH) atomicAdd(&stats[tid], sstat[tid]);
}

// ---------------- BN apply + next-layer pre-transform: p = BN(z) @ wa ----------------
__global__ void __launch_bounds__(256) bnx_k(
    const float* __restrict__ z, const float* __restrict__ stats,
    const float* __restrict__ gamma, const float* __restrict__ beta,
    const float* __restrict__ wa, float* __restrict__ p)
{
    __shared__ __align__(16) float sv[8][HH];
    const int tid = threadIdx.x, warp = tid >> 5, lane = tid & 31;
    float wac[HH];
    #pragma unroll
    for (int k = 0; k < HH; k++) wac[k] = wa[k * HH + lane];
    float mean  = stats[lane] * (1.0f / NN);
    float var   = stats[HH + lane] * (1.0f / NN) - mean * mean;
    float scale = gamma[lane] * rsqrtf(var + BN_EPS);
    float shift = beta[lane] - mean * scale;
    const int base = (blockIdx.x * 8 + warp) * NPW;
    for (int it = 0; it < NPW; it++) {
        int n = base + it;
        if (n >= NN) break;
        float h = z[(size_t)n * HH + lane] * scale + shift;
        sv[warp][lane] = h;
        __syncwarp();
        float o = 0.0f;
        const float4* vv = reinterpret_cast<const float4*>(&sv[warp][0]);
        #pragma unroll
        for (int q = 0; q < HH / 4; q++) {
            float4 v4 = vv[q];
            o += v4.x * wac[4*q+0] + v4.y * wac[4*q+1]
               + v4.z * wac[4*q+2] + v4.w * wac[4*q+3];
        }
        p[(size_t)n * HH + lane] = o;
        __syncwarp();
    }
}

// ---------------- final BN apply + global mean-pool sums ----------------
__global__ void __launch_bounds__(256) bnp_k(
    const float* __restrict__ z, const float* __restrict__ stats,
    const float* __restrict__ gamma, const float* __restrict__ beta,
    const int* __restrict__ batch, float* __restrict__ pool)
{
    __shared__ __align__(16) float sv[8][HH];
    const int tid = threadIdx.x, warp = tid >> 5, lane = tid & 31;
    float mean  = stats[lane] * (1.0f / NN);
    float var   = stats[HH + lane] * (1.0f / NN) - mean * mean;
    float scale = gamma[lane] * rsqrtf(var + BN_EPS);
    float shift = beta[lane] - mean * scale;
    const int base = (blockIdx.x * 8 + warp) * NPW;
    for (int it = 0; it < NPW; it++) {
        int n = base + it;
        if (n >= NN) break;
        float h = z[(size_t)n * HH + lane] * scale + shift;
        sv[warp][lane] = h;
        __syncwarp();
        int g = __ldg(&batch[n]);
        if (lane < HH / 4) {
            float4 v4 = reinterpret_cast<const float4*>(&sv[warp][0])[lane];
            float* a = pool + (size_t)g * HH + lane * 4;
            asm volatile("red.global.add.v4.f32 [%0], {%1,%2,%3,%4};"
                         :: "l"(a), "f"(v4.x), "f"(v4.y), "f"(v4.z), "f"(v4.w) : "memory");
        }
        __syncwarp();
    }
}

// ---------------- head ----------------
__global__ void head_k(const float* __restrict__ pool, const int* __restrict__ batch,
                       const float* __restrict__ fc1w, const float* __restrict__ fc1b,
                       const float* __restrict__ fc2w, const float* __restrict__ fc2b,
                       float* __restrict__ out)
{
    __shared__ float s1[HH * HH], s2[HH * CC], b1[HH], b2[CC];
    const int tid = threadIdx.x;
    for (int i = tid; i < HH * HH; i += GG) s1[i] = fc1w[i];
    for (int i = tid; i < HH * CC; i += GG) s2[i] = fc2w[i];
    if (tid < HH) b1[tid] = fc1b[tid];
    if (tid < CC) b2[tid] = fc2b[tid];
    __syncthreads();
    const int g = tid;
    int lo0 = 0, hi0 = NN;
    while (lo0 < hi0) { int mid = (lo0 + hi0) >> 1; if (batch[mid] < g) lo0 = mid + 1; else hi0 = mid; }
    int lo1 = lo0, hi1 = NN;
    while (lo1 < hi1) { int mid = (lo1 + hi1) >> 1; if (batch[mid] < g + 1) lo1 = mid + 1; else hi1 = mid; }
    float inv = 1.0f / fmaxf((float)(lo1 - lo0), 1.0f);
    float hid[HH];
    #pragma unroll
    for (int j = 0; j < HH; j++) hid[j] = b1[j];
    #pragma unroll
    for (int k = 0; k < HH; k++) {
        float v = pool[g * HH + k] * inv;
        #pragma unroll
        for (int j = 0; j < HH; j++) hid[j] += v * s1[k * HH + j];
    }
    #pragma unroll
    for (int j = 0; j < HH; j++) hid[j] = fmaxf(hid[j], 0.0f);
    float o[CC];
    #pragma unroll
    for (int c = 0; c < CC; c++) o[c] = b2[c];
    #pragma unroll
    for (int k = 0; k < HH; k++) {
        float v = hid[k];
        #pragma unroll
        for (int c = 0; c < CC; c++) o[c] += v * s2[k * CC + c];
    }
    float m = o[0];
    #pragma unroll
    for (int c = 1; c < CC; c++) m = fmaxf(m, o[c]);
    float sum = 0.0f;
    #pragma unroll
    for (int c = 0; c < CC; c++) sum += expf(o[c] - m);
    float lse = m + logf(sum);
    #pragma unroll
    for (int c = 0; c < CC; c++) out[g * CC + c] = o[c] - lse;
}

// ---------------- launch ----------------
extern "C" void kernel_launch(void* const* d_in, const int* in_sizes, int n_in,
                              void* d_out, int out_size)
{
    const float* x     = (const float*)d_in[0];
    const int*   ei    = (const int*)  d_in[1];
    const int*   batch = (const int*)  d_in[2];
    const float* w1a   = (const float*)d_in[3];
    const float* b1a   = (const float*)d_in[4];
    const float* w1b   = (const float*)d_in[5];
    const float* b1b   = (const float*)d_in[6];
    const float* wa    = (const float*)d_in[7];
    const float* ba    = (const float*)d_in[8];
    const float* wb    = (const float*)d_in[9];
    const float* bb    = (const float*)d_in[10];
    const float* gamma = (const float*)d_in[11];
    const float* beta  = (const float*)d_in[12];
    const float* fc1w  = (const float*)d_in[13];
    const float* fc1b  = (const float*)d_in[14];
    const float* fc2w  = (const float*)d_in[15];
    const float* fc2b  = (const float*)d_in[16];
    float* out = (float*)d_out;

    const int E = in_sizes[1] / 2;
    const int* src = ei;
    const int* dst = ei + E;

    int *row, *cur, *col, *part;
    float *p, *z, *stats, *pool;
    cudaGetSymbolAddress((void**)&row,   g_row);
    cudaGetSymbolAddress((void**)&cur,   g_cur);
    cudaGetSymbolAddress((void**)&col,   g_col);
    cudaGetSymbolAddress((void**)&part,  g_part);
    cudaGetSymbolAddress((void**)&p,     g_p);
    cudaGetSymbolAddress((void**)&z,     g_z);
    cudaGetSymbolAddress((void**)&stats, g_stats);
    cudaGetSymbolAddress((void**)&pool,  g_pool);

    // ---- one-time zeroing (off the per-layer critical path) ----
    cudaMemsetAsync(cur,   0, NN * sizeof(int));
    cudaMemsetAsync(stats, 0, 5 * 2 * HH * sizeof(float));
    cudaMemsetAsync(pool,  0, GG * HH * sizeof(float));

    // ---- CSR build ----
    hist_k <<<(E + 255) / 256, 256>>>(dst, cur, E);
    scanA_k<<<SB, 1024>>>(cur, part);
    scanB_k<<<1, 32>>>(part, SB);
    scanC_k<<<SB, 1024>>>(cur, part, row, E);
    fill_k <<<(E + 255) / 256, 256>>>(src, dst, cur, col, E);

    // ---- block-1 pre-transform ----
    xform_k<<<(NN + 255) / 256, 256>>>(x, w1a, p);

    const int GB = NN / 32;   // 3125 blocks; 8 warps x 4 nodes

    // ---- 5 GIN blocks (per-layer stats slots; no inter-layer memsets) ----
    for (int i = 0; i < 5; i++) {
        const float* ba_i = (i == 0) ? b1a : ba + (size_t)(i - 1) * HH;
        const float* wb_i = (i == 0) ? w1b : wb + (size_t)(i - 1) * HH * HH;
        const float* bb_i = (i == 0) ? b1b : bb + (size_t)(i - 1) * HH;
        gmlp_k<<<GB, 256>>>(p, row, col, wb_i, ba_i, bb_i, z,
                            stats + (size_t)i * 2 * HH);
        if (i < 4) {
            bnx_k<<<GB, 256>>>(z, stats + (size_t)i * 2 * HH,
                               gamma + (size_t)i * HH, beta + (size_t)i * HH,
                               wa + (size_t)i * HH * HH, p);
        } else {
            bnp_k<<<GB, 256>>>(z, stats + 4 * 2 * HH,
                               gamma + 4 * HH, beta + 4 * HH, batch, pool);
        }
    }

    // ---- readout ----
    head_k<<<1, GG>>>(pool, batch, fc1w, fc1b, fc2w, fc2b, out);
}